// round 6
// baseline (speedup 1.0000x reference)
#include <cuda_runtime.h>
#include <cooperative_groups.h>
namespace cg = cooperative_groups;

#define B 64
#define NEG_BIG (-3.402823466e38f)

// ---------------- scratch (device globals; no allocation) ----------------
__device__ float g_t1[B * 128 * 128];
__device__ float g_t6[B * 256];                       // LN6-applied FC input
__device__ __align__(16) float g_fcp[4][B * 1024];    // FC partials (k-split 4)
__device__ __align__(16) float g_wT[225536];          // transposed L2..L6 weights
__device__ __align__(16) float g_w1T[16384 * 49];     // transposed L1 weights
__device__ float g_sink;

// wT segment bases (floats)
#define WT2 0
#define WT3 102400
#define WT4 204800
#define WT5 214016
#define WT6 223232
#define WT_TOTAL 225536

// =====================================================================
// Kernel W: transpose L2..L6 weights [p][t] -> tap-major grouped layout
// =====================================================================
__global__ __launch_bounds__(256) void wt_kernel(
    const float* __restrict__ w2, const float* __restrict__ w3,
    const float* __restrict__ w4, const float* __restrict__ w5,
    const float* __restrict__ w6)
{
    int i = blockIdx.x * 256 + threadIdx.x;
    if (i >= WT_TOTAL) return;
    const float* src;
    int off, NPOS, KB;
    if (i < WT3)      { src = w2; off = i;       NPOS = 4096; KB = 25; }
    else if (i < WT4) { src = w3; off = i - WT3; NPOS = 4096; KB = 25; }
    else if (i < WT5) { src = w4; off = i - WT4; NPOS = 1024; KB = 9;  }
    else if (i < WT6) { src = w5; off = i - WT5; NPOS = 1024; KB = 9;  }
    else              { src = w6; off = i - WT6; NPOS = 256;  KB = 9;  }
    int G4 = (KB / 4) * 4;
    int t, p;
    if (off < NPOS * G4) {
        int g = off / (4 * NPOS);
        int r = off % (4 * NPOS);
        p = r >> 2;
        t = 4 * g + (r & 3);
    } else {
        p = off - NPOS * G4;
        t = G4;
    }
    g_wT[i] = src[p * KB + t];
}

// =====================================================================
// Kernel W1: transpose L1 weights tap-major + prewarm fcw into L2.
// =====================================================================
#define W1N 16384
#define W1TOT (W1N * 49)
#define W1BLK 3136
#define FCWBLK 1024

__global__ __launch_bounds__(256) void wt1_kernel(
    const float* __restrict__ w1, const float* __restrict__ fcw)
{
    if (blockIdx.x < W1BLK) {
        int i = blockIdx.x * 256 + threadIdx.x;
        if (i >= W1TOT) return;
        int t, p;
        if (i < W1N * 48) {
            int g = i / (4 * W1N);
            int r = i % (4 * W1N);
            p = r >> 2;
            t = 4 * g + (r & 3);
        } else {
            p = i - W1N * 48;
            t = 48;
        }
        g_w1T[i] = w1[p * 49 + t];
    } else {
        int i2 = (blockIdx.x - W1BLK) * 256 + threadIdx.x;
        float v = fcw[i2];
        if (__float_as_uint(v) == 0x7f800001u) g_sink = v;
    }
}

// =====================================================================
// Kernel A: L1 LC 7x7 -> relu -> g_t1 (unchanged from R5)
// =====================================================================
__global__ __launch_bounds__(256, 2) void l1_kernel(
    const float* __restrict__ x, const float* __restrict__ bias,
    float* __restrict__ out)
{
    __shared__ float xs[38 * 23];

    const int tid = threadIdx.x;
    const int bi = blockIdx.x >> 3;
    const int bj = blockIdx.x & 7;
    const int s0 = blockIdx.y * 8;
    const int oi = tid >> 3;
    const int oj2 = (tid & 7) * 2;
    const int gi = bi * 32 + oi;
    const int gj = bj * 16 + oj2;
    const int p0 = gi * 128 + gj;

    float w0[49], w1r[49];
    const float4* A = (const float4*)g_w1T;
#pragma unroll
    for (int g = 0; g < 12; g++) {
        float4 a0 = A[g * W1N + p0];
        float4 a1 = A[g * W1N + p0 + 1];
        w0[4 * g] = a0.x; w0[4 * g + 1] = a0.y; w0[4 * g + 2] = a0.z; w0[4 * g + 3] = a0.w;
        w1r[4 * g] = a1.x; w1r[4 * g + 1] = a1.y; w1r[4 * g + 2] = a1.z; w1r[4 * g + 3] = a1.w;
    }
    w0[48] = g_w1T[48 * W1N + p0];
    w1r[48] = g_w1T[48 * W1N + p0 + 1];
    const float b0 = bias[p0], b1 = bias[p0 + 1];

    for (int sl = 0; sl < 8; sl++) {
        const int s = s0 + sl;
        __syncthreads();
        for (int idx = tid; idx < 38 * 22; idx += 256) {
            int pr = idx / 22, pc = idx % 22;
            int r = bi * 32 + pr - 3, c = bj * 16 + pc - 3;
            float v = 0.f;
            if (r >= 0 && r < 128 && c >= 0 && c < 128)
                v = x[(s * 128 + r) * 128 + c];
            xs[pr * 23 + pc] = v;
        }
        __syncthreads();

        float acc0 = b0, acc1 = b1;
#pragma unroll
        for (int r = 0; r < 7; r++) {
            float xv[8];
#pragma unroll
            for (int c = 0; c < 8; c++) xv[c] = xs[(oi + r) * 23 + oj2 + c];
#pragma unroll
            for (int c = 0; c < 7; c++) {
                acc0 = fmaf(xv[c], w0[r * 7 + c], acc0);
                acc1 = fmaf(xv[c + 1], w1r[r * 7 + c], acc1);
            }
        }
        float* o = &out[(s * 128 + gi) * 128 + gj];
        o[0] = fmaxf(acc0, 0.f);
        o[1] = fmaxf(acc1, 0.f);
    }
}

// =====================================================================
// Kernel B: fused L2..L6, 2-CTA cluster per sample (half-plane each).
// Stats and halo rows exchanged via DSMEM.
// =====================================================================
__device__ __forceinline__ void stats2(
    cg::cluster_group& cluster, float ls, float lq, float invn,
    float* RED, float* EX, const float* peerEX)
{
#pragma unroll
    for (int o = 16; o > 0; o >>= 1) {
        ls += __shfl_xor_sync(0xffffffffu, ls, o);
        lq += __shfl_xor_sync(0xffffffffu, lq, o);
    }
    const int wid = threadIdx.x >> 5, lane = threadIdx.x & 31;
    if (lane == 0) { RED[wid] = ls; RED[32 + wid] = lq; }
    __syncthreads();
    if (threadIdx.x == 0) {
        float s = 0.f, q = 0.f;
#pragma unroll
        for (int i = 0; i < 32; i++) { s += RED[i]; q += RED[32 + i]; }
        EX[0] = s; EX[1] = q;
    }
    cluster.sync();        // publishes EX, also: peer OUT complete
    if (threadIdx.x == 0) {
        float s = EX[0] + peerEX[0];
        float q = EX[1] + peerEX[1];
        float mu = s * invn;
        float var = q * invn - mu * mu;
        RED[64] = mu;
        RED[65] = rsqrtf(var + 1e-5f);
    }
    __syncthreads();
}

// LC over own half: local output rows li in [0, HO/2), global row own0+li.
template <int HO, int KK, int STRIDE>
__device__ __forceinline__ void lc_split(
    const float* IN, float* OUT, const float* __restrict__ wT,
    const float* __restrict__ bias, int own0, float& ls, float& lq)
{
    constexpr int NPOS = HO * HO;
    constexpr int OWN = NPOS / 2;
    constexpr int KB = KK * KK;
    constexpr int G = KB / 4;
    for (int p0 = 0; p0 < OWN; p0 += 1024) {
        int p = p0 + threadIdx.x;
        if (p < OWN) {
            int li = p / HO, j = p % HO;
            int gp = (own0 + li) * HO + j;
            const float* inb = IN + li * STRIDE + j;
            const float4* A = (const float4*)wT;
            float acc = bias[gp];
#pragma unroll
            for (int g = 0; g < G; g++) {
                float4 wv = A[g * NPOS + gp];
#pragma unroll
                for (int jj = 0; jj < 4; jj++) {
                    int t = 4 * g + jj;
                    int r = t / KK, c = t % KK;
                    float wj = (jj == 0) ? wv.x : (jj == 1) ? wv.y : (jj == 2) ? wv.z : wv.w;
                    acc = fmaf(inb[r * STRIDE + c], wj, acc);
                }
            }
            {
                constexpr int t = KB - 1;
                constexpr int r = t / KK, c = t % KK;
                acc = fmaf(inb[r * STRIDE + c], wT[4 * G * NPOS + gp], acc);
            }
            acc = fmaxf(acc, 0.f);
            OUT[p] = acc;
            ls += acc;
            lq += acc * acc;
        }
    }
}

// zero pad columns (cols [0,PAD) and [HO+PAD,STRIDE)) for ROWS rows
template <int ROWS, int HO, int PAD, int STRIDE>
__device__ __forceinline__ void zero_borders(float* IN)
{
    constexpr int BC = STRIDE - HO;
    for (int i = threadIdx.x; i < ROWS * BC; i += 1024) {
        int r = i / BC, c = i % BC;
        int col = (c < PAD) ? c : HO + c;
        IN[r * STRIDE + col] = 0.f;
    }
}

// LN-apply OUT(H0 plane) -> IN halo'd (own half + PAD rows, peer via DSMEM)
template <int HO, int PAD, int STRIDE>
__device__ __forceinline__ void ln_apply_split(
    const float* OUT, const float* peerOUT, float* IN,
    const float* __restrict__ g, const float* __restrict__ be,
    float mu, float rs, int h)
{
    constexpr int OH = HO / 2;
    constexpr int ROWS = OH + 2 * PAD;
    const int own0 = h * OH;
    zero_borders<ROWS, HO, PAD, STRIDE>(IN);
    for (int p = threadIdx.x; p < ROWS * HO; p += 1024) {
        int ri = p / HO, j = p % HO;
        int gr = own0 - PAD + ri;
        float val = 0.f;
        if (gr >= 0 && gr < HO) {
            bool own = (gr >= own0) && (gr < own0 + OH);
            const float* src = own ? OUT : peerOUT;
            int base = own ? own0 : (h ^ 1) * OH;
            float t = src[(gr - base) * HO + j];
            val = (t - mu) * rs * g[gr * HO + j] + be[gr * HO + j];
        }
        IN[ri * STRIDE + j + PAD] = val;
    }
}

// LN + 2x2 maxpool: OUT at H2=2*HO resolution -> IN pooled (HO plane), halo'd
template <int HO, int PAD, int STRIDE>
__device__ __forceinline__ void ln_pool_split(
    const float* OUT, const float* peerOUT, float* IN,
    const float* __restrict__ g, const float* __restrict__ be,
    float mu, float rs, int h)
{
    constexpr int OH = HO / 2;
    constexpr int H2 = HO * 2;
    constexpr int ROWS = OH + 2 * PAD;
    const int own0 = h * OH;       // pooled own start
    const int ownO2 = h * HO;      // own OUT rows start (H2 plane, HO rows each)
    zero_borders<ROWS, HO, PAD, STRIDE>(IN);
    for (int p = threadIdx.x; p < ROWS * HO; p += 1024) {
        int ri = p / HO, j = p % HO;
        int gr = own0 - PAD + ri;
        float val = 0.f;
        if (gr >= 0 && gr < HO) {
            int r2 = 2 * gr;
            bool own = (r2 >= ownO2) && (r2 < ownO2 + HO);
            const float* src = own ? OUT : peerOUT;
            int base = own ? ownO2 : (h ^ 1) * HO;
            float m = NEG_BIG;
#pragma unroll
            for (int dr = 0; dr < 2; dr++)
#pragma unroll
                for (int dc = 0; dc < 2; dc++) {
                    int grow = r2 + dr, gcol = 2 * j + dc;
                    int gi = grow * H2 + gcol;
                    float t = src[(grow - base) * H2 + gcol];
                    m = fmaxf(m, (t - mu) * rs * g[gi] + be[gi]);
                }
            val = m;
        }
        IN[ri * STRIDE + j + PAD] = val;
    }
}

__global__ __launch_bounds__(1024) __cluster_dims__(2, 1, 1)
void fused_kernel(
    const float* __restrict__ b2, const float* __restrict__ b3,
    const float* __restrict__ b4, const float* __restrict__ b5,
    const float* __restrict__ b6,
    const float* __restrict__ g1, const float* __restrict__ be1,
    const float* __restrict__ g2, const float* __restrict__ be2,
    const float* __restrict__ g3, const float* __restrict__ be3,
    const float* __restrict__ g4, const float* __restrict__ be4,
    const float* __restrict__ g5, const float* __restrict__ be5,
    const float* __restrict__ g6, const float* __restrict__ be6)
{
    __shared__ float IN[36 * 68];
    __shared__ float OUT[32 * 64];
    __shared__ float RED[66];
    __shared__ float EX[2];

    cg::cluster_group cluster = cg::this_cluster();
    const int h = (int)cluster.block_rank();
    const int s = blockIdx.x >> 1;
    const int tid = threadIdx.x;
    float* peerOUT = cluster.map_shared_rank(OUT, h ^ 1);
    const float* peerEX = cluster.map_shared_rank(EX, h ^ 1);
    const float* t1s = g_t1 + s * 16384;

    // ---- LN1 stats over own half of t1 ----
    float ls = 0.f, lq = 0.f;
    {
        const float4* t4 = (const float4*)(t1s + h * 8192);
        for (int i = tid; i < 2048; i += 1024) {
            float4 v = t4[i];
            ls += v.x + v.y + v.z + v.w;
            lq += v.x * v.x + v.y * v.y + v.z * v.z + v.w * v.w;
        }
    }
    stats2(cluster, ls, lq, 1.f / 16384.f, RED, EX, peerEX);
    float mu = RED[64], rs = RED[65];

    // ---- fill IN for L2: LN1 + pool from global t1 (own 32 rows + 2 halo) ----
    zero_borders<36, 64, 2, 68>(IN);
    for (int p = tid; p < 36 * 64; p += 1024) {
        int ri = p >> 6, j = p & 63;
        int gr = h * 32 - 2 + ri;
        float val = 0.f;
        if (gr >= 0 && gr < 64) {
            float m = NEG_BIG;
#pragma unroll
            for (int dr = 0; dr < 2; dr++)
#pragma unroll
                for (int dc = 0; dc < 2; dc++) {
                    int gi = (2 * gr + dr) * 128 + 2 * j + dc;
                    float t = t1s[gi];
                    m = fmaxf(m, (t - mu) * rs * g1[gi] + be1[gi]);
                }
            val = m;
        }
        IN[ri * 68 + j + 2] = val;
    }

    // ---- L2 ----
    cluster.sync();
    ls = lq = 0.f;
    lc_split<64, 5, 68>(IN, OUT, g_wT + WT2, b2, h * 32, ls, lq);
    stats2(cluster, ls, lq, 1.f / 4096.f, RED, EX, peerEX);
    mu = RED[64]; rs = RED[65];
    ln_apply_split<64, 2, 68>(OUT, peerOUT, IN, g2, be2, mu, rs, h);

    // ---- L3 ----
    cluster.sync();
    ls = lq = 0.f;
    lc_split<64, 5, 68>(IN, OUT, g_wT + WT3, b3, h * 32, ls, lq);
    stats2(cluster, ls, lq, 1.f / 4096.f, RED, EX, peerEX);
    mu = RED[64]; rs = RED[65];
    ln_pool_split<32, 1, 34>(OUT, peerOUT, IN, g3, be3, mu, rs, h);

    // ---- L4 ----
    cluster.sync();
    ls = lq = 0.f;
    lc_split<32, 3, 34>(IN, OUT, g_wT + WT4, b4, h * 16, ls, lq);
    stats2(cluster, ls, lq, 1.f / 1024.f, RED, EX, peerEX);
    mu = RED[64]; rs = RED[65];
    ln_apply_split<32, 1, 34>(OUT, peerOUT, IN, g4, be4, mu, rs, h);

    // ---- L5 ----
    cluster.sync();
    ls = lq = 0.f;
    lc_split<32, 3, 34>(IN, OUT, g_wT + WT5, b5, h * 16, ls, lq);
    stats2(cluster, ls, lq, 1.f / 1024.f, RED, EX, peerEX);
    mu = RED[64]; rs = RED[65];
    ln_pool_split<16, 1, 18>(OUT, peerOUT, IN, g5, be5, mu, rs, h);

    // ---- L6 ----
    cluster.sync();
    ls = lq = 0.f;
    lc_split<16, 3, 18>(IN, OUT, g_wT + WT6, b6, h * 8, ls, lq);
    stats2(cluster, ls, lq, 1.f / 256.f, RED, EX, peerEX);
    mu = RED[64]; rs = RED[65];
    if (tid < 128) {
        int gp = h * 128 + tid;
        g_t6[s * 256 + gp] = (OUT[tid] - mu) * rs * g6[gp] + be6[gp];
    }
    cluster.sync();   // no CTA exits while peer may still read its SMEM
}

// =====================================================================
// Kernel C: FC GEMM partials, k-split 4. grid (32, 2, 4) = 256 blocks.
// =====================================================================
__global__ __launch_bounds__(256) void fc_kernel(const float* __restrict__ fcw)
{
    __shared__ float Ws[64 * 34];
    __shared__ float Xs[64 * 34];

    const int tid = threadIdx.x;
    const int o0 = blockIdx.x * 32;
    const int s0 = blockIdx.y * 32;
    const int k0 = blockIdx.z * 64;

    for (int idx = tid; idx < 32 * 64; idx += 256) {
        int o = idx >> 6, k = idx & 63;
        Ws[k * 34 + o] = fcw[(o0 + o) * 256 + k0 + k];
    }
    for (int idx = tid; idx < 32 * 64; idx += 256) {
        int ss = idx >> 6, k = idx & 63;
        Xs[k * 34 + ss] = g_t6[(s0 + ss) * 256 + k0 + k];
    }
    __syncthreads();

    const int oL = (tid & 15) * 2;
    const int sL = (tid >> 4) * 2;
    float a00 = 0.f, a01 = 0.f, a10 = 0.f, a11 = 0.f;
#pragma unroll 8
    for (int k = 0; k < 64; k++) {
        float2 wv = *(const float2*)&Ws[k * 34 + oL];
        float2 xv = *(const float2*)&Xs[k * 34 + sL];
        a00 = fmaf(wv.x, xv.x, a00);
        a10 = fmaf(wv.y, xv.x, a10);
        a01 = fmaf(wv.x, xv.y, a01);
        a11 = fmaf(wv.y, xv.y, a11);
    }
    float* dst = g_fcp[blockIdx.z];
    dst[(s0 + sL) * 1024 + o0 + oL] = a00;
    dst[(s0 + sL) * 1024 + o0 + oL + 1] = a10;
    dst[(s0 + sL + 1) * 1024 + o0 + oL] = a01;
    dst[(s0 + sL + 1) * 1024 + o0 + oL + 1] = a11;
}

// =====================================================================
// Kernel D: combine 4 FC partials + bias, softmax (shuffle reductions).
// =====================================================================
__global__ __launch_bounds__(256) void softmax_kernel(
    const float* __restrict__ fcb, float* __restrict__ out)
{
    __shared__ float red1[8];
    __shared__ float red2[8];
    const int s = blockIdx.x, tid = threadIdx.x;
    const int wid = tid >> 5, lane = tid & 31;

    const float4* p0 = (const float4*)&g_fcp[0][s * 1024];
    const float4* p1 = (const float4*)&g_fcp[1][s * 1024];
    const float4* p2 = (const float4*)&g_fcp[2][s * 1024];
    const float4* p3 = (const float4*)&g_fcp[3][s * 1024];
    const float4* pb = (const float4*)fcb;
    float4 a = p0[tid], b = p1[tid], c = p2[tid], d = p3[tid], e = pb[tid];
    float4 v;
    v.x = a.x + b.x + c.x + d.x + e.x;
    v.y = a.y + b.y + c.y + d.y + e.y;
    v.z = a.z + b.z + c.z + d.z + e.z;
    v.w = a.w + b.w + c.w + d.w + e.w;

    float m = fmaxf(fmaxf(v.x, v.y), fmaxf(v.z, v.w));
#pragma unroll
    for (int o = 16; o > 0; o >>= 1) m = fmaxf(m, __shfl_xor_sync(0xffffffffu, m, o));
    if (lane == 0) red1[wid] = m;
    __syncthreads();
    m = red1[0];
#pragma unroll
    for (int i = 1; i < 8; i++) m = fmaxf(m, red1[i]);

    v.x = __expf(v.x - m);
    v.y = __expf(v.y - m);
    v.z = __expf(v.z - m);
    v.w = __expf(v.w - m);
    float sum = v.x + v.y + v.z + v.w;
#pragma unroll
    for (int o = 16; o > 0; o >>= 1) sum += __shfl_xor_sync(0xffffffffu, sum, o);
    if (lane == 0) red2[wid] = sum;
    __syncthreads();
    float tot = 0.f;
#pragma unroll
    for (int i = 0; i < 8; i++) tot += red2[i];
    const float inv = 1.f / tot;

    float4 r;
    r.x = v.x * inv; r.y = v.y * inv; r.z = v.z * inv; r.w = v.w * inv;
    ((float4*)&out[s * 1024])[tid] = r;
}

// ---------------- launch ----------------
extern "C" void kernel_launch(void* const* d_in, const int* in_sizes, int n_in,
                              void* d_out, int out_size)
{
    const float* X = (const float*)d_in[0];
    const float* W[6];
    const float* Bi[6];
    const float* G[6];
    const float* Be[6];
    for (int i = 0; i < 6; i++) {
        W[i]  = (const float*)d_in[1 + 4 * i];
        Bi[i] = (const float*)d_in[2 + 4 * i];
        G[i]  = (const float*)d_in[3 + 4 * i];
        Be[i] = (const float*)d_in[4 + 4 * i];
    }
    const float* FCW = (const float*)d_in[25];
    const float* FCB = (const float*)d_in[26];

    float* t1;
    cudaGetSymbolAddress((void**)&t1, g_t1);

    wt_kernel<<<(WT_TOTAL + 255) / 256, 256>>>(W[1], W[2], W[3], W[4], W[5]);
    wt1_kernel<<<W1BLK + FCWBLK, 256>>>(W[0], FCW);

    l1_kernel<<<dim3(32, 8), 256>>>(X, Bi[0], t1);

    fused_kernel<<<128, 1024>>>(
        Bi[1], Bi[2], Bi[3], Bi[4], Bi[5],
        G[0], Be[0], G[1], Be[1], G[2], Be[2],
        G[3], Be[3], G[4], Be[4], G[5], Be[5]);

    fc_kernel<<<dim3(32, 2, 4), 256>>>(FCW);
    softmax_kernel<<<64, 256>>>(FCB, (float*)d_out);
}

// round 7
// speedup vs baseline: 1.0883x; 1.0883x over previous
#include <cuda_runtime.h>
#include <cooperative_groups.h>
namespace cg = cooperative_groups;

#define B 64
#define NEG_BIG (-3.402823466e38f)

// ---------------- scratch (device globals; no allocation) ----------------
__device__ float g_t1[B * 128 * 128];
__device__ float g_t6[B * 256];                       // LN6-applied FC input
__device__ __align__(16) float g_fcp[4][B * 1024];    // FC partials (k-split 4)
__device__ __align__(16) float g_wT[225536];          // transposed L2..L6 weights
__device__ __align__(16) float g_w1T[16384 * 49];     // transposed L1 weights
__device__ float g_sink;

// wT segment bases (floats)
#define WT2 0
#define WT3 102400
#define WT4 204800
#define WT5 214016
#define WT6 223232
#define WT_TOTAL 225536

// =====================================================================
// Kernel W: transpose L2..L6 weights [p][t] -> tap-major grouped layout
// =====================================================================
__global__ __launch_bounds__(256) void wt_kernel(
    const float* __restrict__ w2, const float* __restrict__ w3,
    const float* __restrict__ w4, const float* __restrict__ w5,
    const float* __restrict__ w6)
{
    int i = blockIdx.x * 256 + threadIdx.x;
    if (i >= WT_TOTAL) return;
    const float* src;
    int off, NPOS, KB;
    if (i < WT3)      { src = w2; off = i;       NPOS = 4096; KB = 25; }
    else if (i < WT4) { src = w3; off = i - WT3; NPOS = 4096; KB = 25; }
    else if (i < WT5) { src = w4; off = i - WT4; NPOS = 1024; KB = 9;  }
    else if (i < WT6) { src = w5; off = i - WT5; NPOS = 1024; KB = 9;  }
    else              { src = w6; off = i - WT6; NPOS = 256;  KB = 9;  }
    int G4 = (KB / 4) * 4;
    int t, p;
    if (off < NPOS * G4) {
        int g = off / (4 * NPOS);
        int r = off % (4 * NPOS);
        p = r >> 2;
        t = 4 * g + (r & 3);
    } else {
        p = off - NPOS * G4;
        t = G4;
    }
    g_wT[i] = src[p * KB + t];
}

// =====================================================================
// Kernel W1: transpose L1 weights tap-major + prewarm fcw into L2.
// =====================================================================
#define W1N 16384
#define W1TOT (W1N * 49)
#define W1BLK 3136
#define FCWBLK 1024

__global__ __launch_bounds__(256) void wt1_kernel(
    const float* __restrict__ w1, const float* __restrict__ fcw)
{
    if (blockIdx.x < W1BLK) {
        int i = blockIdx.x * 256 + threadIdx.x;
        if (i >= W1TOT) return;
        int t, p;
        if (i < W1N * 48) {
            int g = i / (4 * W1N);
            int r = i % (4 * W1N);
            p = r >> 2;
            t = 4 * g + (r & 3);
        } else {
            p = i - W1N * 48;
            t = 48;
        }
        g_w1T[i] = w1[p * 49 + t];
    } else {
        int i2 = (blockIdx.x - W1BLK) * 256 + threadIdx.x;
        float v = fcw[i2];
        if (__float_as_uint(v) == 0x7f800001u) g_sink = v;
    }
}

// =====================================================================
// Kernel A: L1 LC 7x7 -> relu -> g_t1 (unchanged)
// =====================================================================
__global__ __launch_bounds__(256, 2) void l1_kernel(
    const float* __restrict__ x, const float* __restrict__ bias,
    float* __restrict__ out)
{
    __shared__ float xs[38 * 23];

    const int tid = threadIdx.x;
    const int bi = blockIdx.x >> 3;
    const int bj = blockIdx.x & 7;
    const int s0 = blockIdx.y * 8;
    const int oi = tid >> 3;
    const int oj2 = (tid & 7) * 2;
    const int gi = bi * 32 + oi;
    const int gj = bj * 16 + oj2;
    const int p0 = gi * 128 + gj;

    float w0[49], w1r[49];
    const float4* A = (const float4*)g_w1T;
#pragma unroll
    for (int g = 0; g < 12; g++) {
        float4 a0 = A[g * W1N + p0];
        float4 a1 = A[g * W1N + p0 + 1];
        w0[4 * g] = a0.x; w0[4 * g + 1] = a0.y; w0[4 * g + 2] = a0.z; w0[4 * g + 3] = a0.w;
        w1r[4 * g] = a1.x; w1r[4 * g + 1] = a1.y; w1r[4 * g + 2] = a1.z; w1r[4 * g + 3] = a1.w;
    }
    w0[48] = g_w1T[48 * W1N + p0];
    w1r[48] = g_w1T[48 * W1N + p0 + 1];
    const float b0 = bias[p0], b1 = bias[p0 + 1];

    for (int sl = 0; sl < 8; sl++) {
        const int s = s0 + sl;
        __syncthreads();
        for (int idx = tid; idx < 38 * 22; idx += 256) {
            int pr = idx / 22, pc = idx % 22;
            int r = bi * 32 + pr - 3, c = bj * 16 + pc - 3;
            float v = 0.f;
            if (r >= 0 && r < 128 && c >= 0 && c < 128)
                v = x[(s * 128 + r) * 128 + c];
            xs[pr * 23 + pc] = v;
        }
        __syncthreads();

        float acc0 = b0, acc1 = b1;
#pragma unroll
        for (int r = 0; r < 7; r++) {
            float xv[8];
#pragma unroll
            for (int c = 0; c < 8; c++) xv[c] = xs[(oi + r) * 23 + oj2 + c];
#pragma unroll
            for (int c = 0; c < 7; c++) {
                acc0 = fmaf(xv[c], w0[r * 7 + c], acc0);
                acc1 = fmaf(xv[c + 1], w1r[r * 7 + c], acc1);
            }
        }
        float* o = &out[(s * 128 + gi) * 128 + gj];
        o[0] = fmaxf(acc0, 0.f);
        o[1] = fmaxf(acc1, 0.f);
    }
}

// =====================================================================
// Kernel B: fused L2..L6, 2-CTA cluster per sample, DOUBLE-BUFFERED
// OUT/EX -> only ONE cluster.sync per phase (inside stats2).
// =====================================================================
__device__ __forceinline__ void stats2(
    cg::cluster_group& cluster, float ls, float lq, float invn,
    float* RED, float* EXs, const float* peerEXs)
{
#pragma unroll
    for (int o = 16; o > 0; o >>= 1) {
        ls += __shfl_xor_sync(0xffffffffu, ls, o);
        lq += __shfl_xor_sync(0xffffffffu, lq, o);
    }
    const int wid = threadIdx.x >> 5, lane = threadIdx.x & 31;
    if (lane == 0) { RED[wid] = ls; RED[32 + wid] = lq; }
    __syncthreads();
    if (threadIdx.x == 0) {
        float s = 0.f, q = 0.f;
#pragma unroll
        for (int i = 0; i < 32; i++) { s += RED[i]; q += RED[32 + i]; }
        EXs[0] = s; EXs[1] = q;
    }
    cluster.sync();        // publishes EXs; also: both CTAs' OUT complete
    if (threadIdx.x == 0) {
        float s = EXs[0] + peerEXs[0];
        float q = EXs[1] + peerEXs[1];
        float mu = s * invn;
        float var = q * invn - mu * mu;
        RED[64] = mu;
        RED[65] = rsqrtf(var + 1e-5f);
    }
    __syncthreads();
}

template <int HO, int KK, int STRIDE>
__device__ __forceinline__ void lc_split(
    const float* IN, float* OUT, const float* __restrict__ wT,
    const float* __restrict__ bias, int own0, float& ls, float& lq)
{
    constexpr int NPOS = HO * HO;
    constexpr int OWN = NPOS / 2;
    constexpr int KB = KK * KK;
    constexpr int G = KB / 4;
    for (int p0 = 0; p0 < OWN; p0 += 1024) {
        int p = p0 + threadIdx.x;
        if (p < OWN) {
            int li = p / HO, j = p % HO;
            int gp = (own0 + li) * HO + j;
            const float* inb = IN + li * STRIDE + j;
            const float4* A = (const float4*)wT;
            float acc = bias[gp];
#pragma unroll
            for (int g = 0; g < G; g++) {
                float4 wv = A[g * NPOS + gp];
#pragma unroll
                for (int jj = 0; jj < 4; jj++) {
                    int t = 4 * g + jj;
                    int r = t / KK, c = t % KK;
                    float wj = (jj == 0) ? wv.x : (jj == 1) ? wv.y : (jj == 2) ? wv.z : wv.w;
                    acc = fmaf(inb[r * STRIDE + c], wj, acc);
                }
            }
            {
                constexpr int t = KB - 1;
                constexpr int r = t / KK, c = t % KK;
                acc = fmaf(inb[r * STRIDE + c], wT[4 * G * NPOS + gp], acc);
            }
            acc = fmaxf(acc, 0.f);
            OUT[p] = acc;
            ls += acc;
            lq += acc * acc;
        }
    }
}

template <int ROWS, int HO, int PAD, int STRIDE>
__device__ __forceinline__ void zero_borders(float* IN)
{
    constexpr int BC = STRIDE - HO;
    for (int i = threadIdx.x; i < ROWS * BC; i += 1024) {
        int r = i / BC, c = i % BC;
        int col = (c < PAD) ? c : HO + c;
        IN[r * STRIDE + col] = 0.f;
    }
}

template <int HO, int PAD, int STRIDE>
__device__ __forceinline__ void ln_apply_split(
    const float* OUT, const float* peerOUT, float* IN,
    const float* __restrict__ g, const float* __restrict__ be,
    float mu, float rs, int h)
{
    constexpr int OH = HO / 2;
    constexpr int ROWS = OH + 2 * PAD;
    const int own0 = h * OH;
    zero_borders<ROWS, HO, PAD, STRIDE>(IN);
    for (int p = threadIdx.x; p < ROWS * HO; p += 1024) {
        int ri = p / HO, j = p % HO;
        int gr = own0 - PAD + ri;
        float val = 0.f;
        if (gr >= 0 && gr < HO) {
            bool own = (gr >= own0) && (gr < own0 + OH);
            const float* src = own ? OUT : peerOUT;
            int base = own ? own0 : (h ^ 1) * OH;
            float t = src[(gr - base) * HO + j];
            val = (t - mu) * rs * g[gr * HO + j] + be[gr * HO + j];
        }
        IN[ri * STRIDE + j + PAD] = val;
    }
}

template <int HO, int PAD, int STRIDE>
__device__ __forceinline__ void ln_pool_split(
    const float* OUT, const float* peerOUT, float* IN,
    const float* __restrict__ g, const float* __restrict__ be,
    float mu, float rs, int h)
{
    constexpr int OH = HO / 2;
    constexpr int H2 = HO * 2;
    constexpr int ROWS = OH + 2 * PAD;
    const int own0 = h * OH;
    const int ownO2 = h * HO;
    zero_borders<ROWS, HO, PAD, STRIDE>(IN);
    for (int p = threadIdx.x; p < ROWS * HO; p += 1024) {
        int ri = p / HO, j = p % HO;
        int gr = own0 - PAD + ri;
        float val = 0.f;
        if (gr >= 0 && gr < HO) {
            int r2 = 2 * gr;
            bool own = (r2 >= ownO2) && (r2 < ownO2 + HO);
            const float* src = own ? OUT : peerOUT;
            int base = own ? ownO2 : (h ^ 1) * HO;
            float m = NEG_BIG;
#pragma unroll
            for (int dr = 0; dr < 2; dr++)
#pragma unroll
                for (int dc = 0; dc < 2; dc++) {
                    int grow = r2 + dr, gcol = 2 * j + dc;
                    int gi = grow * H2 + gcol;
                    float t = src[(grow - base) * H2 + gcol];
                    m = fmaxf(m, (t - mu) * rs * g[gi] + be[gi]);
                }
            val = m;
        }
        IN[ri * STRIDE + j + PAD] = val;
    }
}

__global__ __launch_bounds__(1024) __cluster_dims__(2, 1, 1)
void fused_kernel(
    const float* __restrict__ b2, const float* __restrict__ b3,
    const float* __restrict__ b4, const float* __restrict__ b5,
    const float* __restrict__ b6,
    const float* __restrict__ g1, const float* __restrict__ be1,
    const float* __restrict__ g2, const float* __restrict__ be2,
    const float* __restrict__ g3, const float* __restrict__ be3,
    const float* __restrict__ g4, const float* __restrict__ be4,
    const float* __restrict__ g5, const float* __restrict__ be5,
    const float* __restrict__ g6, const float* __restrict__ be6)
{
    __shared__ float IN[36 * 68];
    __shared__ float OUTbuf[2][32 * 64];   // ping-pong across layers
    __shared__ float RED[66];
    __shared__ float EX[4];                // ping-pong (2 floats each)

    cg::cluster_group cluster = cg::this_cluster();
    const int h = (int)cluster.block_rank();
    const int s = blockIdx.x >> 1;
    const int tid = threadIdx.x;
    float* peerOUT0 = cluster.map_shared_rank(OUTbuf[0], h ^ 1);
    float* peerOUT1 = cluster.map_shared_rank(OUTbuf[1], h ^ 1);
    float* peerEXb = cluster.map_shared_rank(EX, h ^ 1);
    const float* t1s = g_t1 + s * 16384;

    // ---- phase 0: LN1 stats over own half of t1 (EX slot 0) ----
    float ls = 0.f, lq = 0.f;
    {
        const float4* t4 = (const float4*)(t1s + h * 8192);
        for (int i = tid; i < 2048; i += 1024) {
            float4 v = t4[i];
            ls += v.x + v.y + v.z + v.w;
            lq += v.x * v.x + v.y * v.y + v.z * v.z + v.w * v.w;
        }
    }
    stats2(cluster, ls, lq, 1.f / 16384.f, RED, EX + 0, peerEXb + 0);
    float mu = RED[64], rs = RED[65];

    // ---- fill IN for L2 from global t1 ----
    zero_borders<36, 64, 2, 68>(IN);
    for (int p = tid; p < 36 * 64; p += 1024) {
        int ri = p >> 6, j = p & 63;
        int gr = h * 32 - 2 + ri;
        float val = 0.f;
        if (gr >= 0 && gr < 64) {
            float m = NEG_BIG;
#pragma unroll
            for (int dr = 0; dr < 2; dr++)
#pragma unroll
                for (int dc = 0; dc < 2; dc++) {
                    int gi = (2 * gr + dr) * 128 + 2 * j + dc;
                    float t = t1s[gi];
                    m = fmaxf(m, (t - mu) * rs * g1[gi] + be1[gi]);
                }
            val = m;
        }
        IN[ri * 68 + j + 2] = val;
    }
    __syncthreads();                       // IN ready for L2

    // ---- L2 (OUT buf 0, EX slot 1) ----
    ls = lq = 0.f;
    lc_split<64, 5, 68>(IN, OUTbuf[0], g_wT + WT2, b2, h * 32, ls, lq);
    stats2(cluster, ls, lq, 1.f / 4096.f, RED, EX + 2, peerEXb + 2);
    mu = RED[64]; rs = RED[65];
    ln_apply_split<64, 2, 68>(OUTbuf[0], peerOUT0, IN, g2, be2, mu, rs, h);
    __syncthreads();

    // ---- L3 (OUT buf 1, EX slot 0) ----
    ls = lq = 0.f;
    lc_split<64, 5, 68>(IN, OUTbuf[1], g_wT + WT3, b3, h * 32, ls, lq);
    stats2(cluster, ls, lq, 1.f / 4096.f, RED, EX + 0, peerEXb + 0);
    mu = RED[64]; rs = RED[65];
    ln_pool_split<32, 1, 34>(OUTbuf[1], peerOUT1, IN, g3, be3, mu, rs, h);
    __syncthreads();

    // ---- L4 (OUT buf 0, EX slot 1) ----
    ls = lq = 0.f;
    lc_split<32, 3, 34>(IN, OUTbuf[0], g_wT + WT4, b4, h * 16, ls, lq);
    stats2(cluster, ls, lq, 1.f / 1024.f, RED, EX + 2, peerEXb + 2);
    mu = RED[64]; rs = RED[65];
    ln_apply_split<32, 1, 34>(OUTbuf[0], peerOUT0, IN, g4, be4, mu, rs, h);
    __syncthreads();

    // ---- L5 (OUT buf 1, EX slot 0) ----
    ls = lq = 0.f;
    lc_split<32, 3, 34>(IN, OUTbuf[1], g_wT + WT5, b5, h * 16, ls, lq);
    stats2(cluster, ls, lq, 1.f / 1024.f, RED, EX + 0, peerEXb + 0);
    mu = RED[64]; rs = RED[65];
    ln_pool_split<16, 1, 18>(OUTbuf[1], peerOUT1, IN, g5, be5, mu, rs, h);
    __syncthreads();

    // ---- L6 (OUT buf 0, EX slot 1) ----
    ls = lq = 0.f;
    lc_split<16, 3, 18>(IN, OUTbuf[0], g_wT + WT6, b6, h * 8, ls, lq);
    stats2(cluster, ls, lq, 1.f / 256.f, RED, EX + 2, peerEXb + 2);
    mu = RED[64]; rs = RED[65];
    if (tid < 128) {
        int gp = h * 128 + tid;
        g_t6[s * 256 + gp] = (OUTbuf[0][tid] - mu) * rs * g6[gp] + be6[gp];
    }
    cluster.sync();   // peer may still be reading our EX; hold SMEM until done
}

// =====================================================================
// Kernel C: FC GEMM partials, k-split 4. grid (32, 2, 4) = 256 blocks.
// =====================================================================
__global__ __launch_bounds__(256) void fc_kernel(const float* __restrict__ fcw)
{
    __shared__ float Ws[64 * 34];
    __shared__ float Xs[64 * 34];

    const int tid = threadIdx.x;
    const int o0 = blockIdx.x * 32;
    const int s0 = blockIdx.y * 32;
    const int k0 = blockIdx.z * 64;

    for (int idx = tid; idx < 32 * 64; idx += 256) {
        int o = idx >> 6, k = idx & 63;
        Ws[k * 34 + o] = fcw[(o0 + o) * 256 + k0 + k];
    }
    for (int idx = tid; idx < 32 * 64; idx += 256) {
        int ss = idx >> 6, k = idx & 63;
        Xs[k * 34 + ss] = g_t6[(s0 + ss) * 256 + k0 + k];
    }
    __syncthreads();

    const int oL = (tid & 15) * 2;
    const int sL = (tid >> 4) * 2;
    float a00 = 0.f, a01 = 0.f, a10 = 0.f, a11 = 0.f;
#pragma unroll 8
    for (int k = 0; k < 64; k++) {
        float2 wv = *(const float2*)&Ws[k * 34 + oL];
        float2 xv = *(const float2*)&Xs[k * 34 + sL];
        a00 = fmaf(wv.x, xv.x, a00);
        a10 = fmaf(wv.y, xv.x, a10);
        a01 = fmaf(wv.x, xv.y, a01);
        a11 = fmaf(wv.y, xv.y, a11);
    }
    float* dst = g_fcp[blockIdx.z];
    dst[(s0 + sL) * 1024 + o0 + oL] = a00;
    dst[(s0 + sL) * 1024 + o0 + oL + 1] = a10;
    dst[(s0 + sL + 1) * 1024 + o0 + oL] = a01;
    dst[(s0 + sL + 1) * 1024 + o0 + oL + 1] = a11;
}

// =====================================================================
// Kernel D: combine 4 FC partials + bias, softmax (shuffle reductions).
// =====================================================================
__global__ __launch_bounds__(256) void softmax_kernel(
    const float* __restrict__ fcb, float* __restrict__ out)
{
    __shared__ float red1[8];
    __shared__ float red2[8];
    const int s = blockIdx.x, tid = threadIdx.x;
    const int wid = tid >> 5, lane = tid & 31;

    const float4* p0 = (const float4*)&g_fcp[0][s * 1024];
    const float4* p1 = (const float4*)&g_fcp[1][s * 1024];
    const float4* p2 = (const float4*)&g_fcp[2][s * 1024];
    const float4* p3 = (const float4*)&g_fcp[3][s * 1024];
    const float4* pb = (const float4*)fcb;
    float4 a = p0[tid], b = p1[tid], c = p2[tid], d = p3[tid], e = pb[tid];
    float4 v;
    v.x = a.x + b.x + c.x + d.x + e.x;
    v.y = a.y + b.y + c.y + d.y + e.y;
    v.z = a.z + b.z + c.z + d.z + e.z;
    v.w = a.w + b.w + c.w + d.w + e.w;

    float m = fmaxf(fmaxf(v.x, v.y), fmaxf(v.z, v.w));
#pragma unroll
    for (int o = 16; o > 0; o >>= 1) m = fmaxf(m, __shfl_xor_sync(0xffffffffu, m, o));
    if (lane == 0) red1[wid] = m;
    __syncthreads();
    m = red1[0];
#pragma unroll
    for (int i = 1; i < 8; i++) m = fmaxf(m, red1[i]);

    v.x = __expf(v.x - m);
    v.y = __expf(v.y - m);
    v.z = __expf(v.z - m);
    v.w = __expf(v.w - m);
    float sum = v.x + v.y + v.z + v.w;
#pragma unroll
    for (int o = 16; o > 0; o >>= 1) sum += __shfl_xor_sync(0xffffffffu, sum, o);
    if (lane == 0) red2[wid] = sum;
    __syncthreads();
    float tot = 0.f;
#pragma unroll
    for (int i = 0; i < 8; i++) tot += red2[i];
    const float inv = 1.f / tot;

    float4 r;
    r.x = v.x * inv; r.y = v.y * inv; r.z = v.z * inv; r.w = v.w * inv;
    ((float4*)&out[s * 1024])[tid] = r;
}

// ---------------- launch ----------------
extern "C" void kernel_launch(void* const* d_in, const int* in_sizes, int n_in,
                              void* d_out, int out_size)
{
    const float* X = (const float*)d_in[0];
    const float* W[6];
    const float* Bi[6];
    const float* G[6];
    const float* Be[6];
    for (int i = 0; i < 6; i++) {
        W[i]  = (const float*)d_in[1 + 4 * i];
        Bi[i] = (const float*)d_in[2 + 4 * i];
        G[i]  = (const float*)d_in[3 + 4 * i];
        Be[i] = (const float*)d_in[4 + 4 * i];
    }
    const float* FCW = (const float*)d_in[25];
    const float* FCB = (const float*)d_in[26];

    float* t1;
    cudaGetSymbolAddress((void**)&t1, g_t1);

    wt_kernel<<<(WT_TOTAL + 255) / 256, 256>>>(W[1], W[2], W[3], W[4], W[5]);
    wt1_kernel<<<W1BLK + FCWBLK, 256>>>(W[0], FCW);

    l1_kernel<<<dim3(32, 8), 256>>>(X, Bi[0], t1);

    fused_kernel<<<128, 1024>>>(
        Bi[1], Bi[2], Bi[3], Bi[4], Bi[5],
        G[0], Be[0], G[1], Be[1], G[2], Be[2],
        G[3], Be[3], G[4], Be[4], G[5], Be[5]);

    fc_kernel<<<dim3(32, 2, 4), 256>>>(FCW);
    softmax_kernel<<<64, 256>>>(FCB, (float*)d_out);
}